// round 2
// baseline (speedup 1.0000x reference)
#include <cuda_runtime.h>
#include <math.h>

#define NB   64
#define NN   5000
#define CC   64
#define DD   10
#define XSTRIDE ((size_t)NN * CC)   // per-batch stride in x / y1 (320000)

// ---------------- scratch (device globals, no allocations) ----------------
__device__ float g_P  [(size_t)NN * NN];        // exp(relu(E E^T)), unnormalized (100 MB)
__device__ float g_inv[NN];                      // 1 / row-sum
__device__ float g_y1 [(size_t)NB * NN * CC];    // support @ x            (82 MB)
__device__ float g_W  [(size_t)NN * 2 * CC * CC];// per-node weights       (164 MB)

// ---------------- f32x2 helpers (Blackwell packed fp32) ----------------
__device__ __forceinline__ unsigned long long pack_dup(float v) {
    unsigned long long r;
    asm("mov.b64 %0, {%1, %1};" : "=l"(r) : "f"(v));
    return r;
}
__device__ __forceinline__ void ffma2(unsigned long long &d,
                                      unsigned long long a,
                                      unsigned long long b) {
    asm("fma.rn.f32x2 %0, %1, %2, %0;" : "+l"(d) : "l"(a), "l"(b));
}
__device__ __forceinline__ float2 unpack2(unsigned long long v) {
    float2 f;
    asm("mov.b64 {%0, %1}, %2;" : "=f"(f.x), "=f"(f.y) : "l"(v));
    return f;
}

// ============================================================================
// Kernel 1: g_P[n][m] = exp(relu(E[n]·E[m])), g_inv[n] = 1/sum_m
// 8 rows per block, 256 threads loop over m (coalesced writes per row).
// ============================================================================
__global__ __launch_bounds__(256) void k_support(const float* __restrict__ E) {
    const int n0 = blockIdx.x * 8;
    float e[8][DD];
#pragma unroll
    for (int r = 0; r < 8; r++)
#pragma unroll
        for (int d = 0; d < DD; d++)
            e[r][d] = __ldg(&E[(size_t)(n0 + r) * DD + d]);

    float sum[8];
#pragma unroll
    for (int r = 0; r < 8; r++) sum[r] = 0.f;

    for (int m = threadIdx.x; m < NN; m += 256) {
        float em[DD];
#pragma unroll
        for (int d = 0; d < DD; d++) em[d] = __ldg(&E[(size_t)m * DD + d]);
#pragma unroll
        for (int r = 0; r < 8; r++) {
            float dot = 0.f;
#pragma unroll
            for (int d = 0; d < DD; d++) dot = fmaf(e[r][d], em[d], dot);
            float v = expf(fmaxf(dot, 0.f));   // relu(dot) <= ~45 -> exp ~3e19, safe in fp32
            g_P[(size_t)(n0 + r) * NN + m] = v;
            sum[r] += v;
        }
    }

    __shared__ float ss[8][256];
#pragma unroll
    for (int r = 0; r < 8; r++) ss[r][threadIdx.x] = sum[r];
    __syncthreads();
    int wid = threadIdx.x >> 5, lane = threadIdx.x & 31;
    float v = 0.f;
#pragma unroll
    for (int i = 0; i < 8; i++) v += ss[wid][lane + i * 32];
#pragma unroll
    for (int o = 16; o > 0; o >>= 1) v += __shfl_xor_sync(0xffffffffu, v, o);
    if (lane == 0) g_inv[n0 + wid] = 1.0f / v;
}

// ============================================================================
// Kernel 2: per-node weights  g_W[n][k][i][o] = sum_d E[n][d]*wp[d][k][i][o]
// grid (32 j-tiles of 256, 20 n-chunks of 250). wp column kept in registers.
// ============================================================================
__global__ __launch_bounds__(256) void k_weights(const float* __restrict__ E,
                                                 const float* __restrict__ wp) {
    const int jb = blockIdx.x;          // 0..31  (256 outputs of 8192)
    const int n0 = blockIdx.y * 250;    // 0..19
    const int tid = threadIdx.x;

    float w[DD];
#pragma unroll
    for (int d = 0; d < DD; d++)
        w[d] = __ldg(&wp[(size_t)d * 8192 + jb * 256 + tid]);

    __shared__ float sE[250 * DD];
    for (int i = tid; i < 250 * DD; i += 256)
        sE[i] = E[(size_t)n0 * DD + i];
    __syncthreads();

    for (int nl = 0; nl < 250; nl++) {
        float acc = 0.f;
#pragma unroll
        for (int d = 0; d < DD; d++)
            acc = fmaf(sE[nl * DD + d], w[d], acc);
        g_W[(size_t)(n0 + nl) * 8192 + jb * 256 + tid] = acc;
    }
}

// ============================================================================
// Kernel 3: the big GEMM.  y1 = (1/rowsum) * P @ Xmat
//   M=5000 rows (n), Ncol=4096 (j = b*64+c), K=5000 (m)
//   128x128x16 tiles, 256 threads, 8x8 per-thread microtile computed as
//   f32x2 pairs along columns.  A tile stored DUPLICATED in SMEM so (a,a)
//   pairs load with one LDS.64 broadcast; B pairs come free from LDS.128.
// ============================================================================
#define BK    16
#define AS_LD 264           // 2*128 + 8 pad
#define NT    313           // ceil(5000/16)

__global__ __launch_bounds__(256, 2) void k_gemm(const float* __restrict__ x) {
    __shared__ __align__(16) float As2[BK * AS_LD];
    __shared__ __align__(16) float Bs [BK * 128];

    const int tid = threadIdx.x;
    const int bx = blockIdx.x;        // 32 column tiles
    const int by = blockIdx.y;        // 40 row tiles
    const int tx = tid & 15, ty = tid >> 4;

    // A-load mapping: k = tid&15 (fixed), rows = tid>>4 + 16t
    const int a_k = tid & 15;
    const int a_r = tid >> 4;
    const int row_base = by * 128 + a_r;
    // B-load mapping: j = tid&127, k = tid>>7 + 2t
    const int b_j = tid & 127;
    const int b_k = tid >> 7;
    const int jg  = bx * 128 + b_j;
    const float* xcol = x + (size_t)(jg >> 6) * XSTRIDE + (jg & 63);

    float rA[8], rB[8];
#pragma unroll
    for (int t = 0; t < 8; t++) {
        int r = row_base + 16 * t;
        rA[t] = (r < NN) ? g_P[(size_t)r * NN + a_k] : 0.f;
    }
#pragma unroll
    for (int t = 0; t < 8; t++) {
        int k = b_k + 2 * t;
        rB[t] = (k < NN) ? __ldg(&xcol[(size_t)k * CC]) : 0.f;
    }

    unsigned long long acc[8][4];
#pragma unroll
    for (int r = 0; r < 8; r++)
#pragma unroll
        for (int c = 0; c < 4; c++) acc[r][c] = 0ull;

    for (int kt = 0; kt < NT; kt++) {
        __syncthreads();
#pragma unroll
        for (int t = 0; t < 8; t++)
            *(unsigned long long*)&As2[a_k * AS_LD + 2 * a_r + 32 * t] = pack_dup(rA[t]);
#pragma unroll
        for (int t = 0; t < 8; t++)
            Bs[tid + 256 * t] = rB[t];
        __syncthreads();

        if (kt + 1 < NT) {
            const int kb = (kt + 1) * 16;
#pragma unroll
            for (int t = 0; t < 8; t++) {
                int r = row_base + 16 * t;
                int k = kb + a_k;
                rA[t] = (r < NN && k < NN) ? g_P[(size_t)r * NN + k] : 0.f;
            }
#pragma unroll
            for (int t = 0; t < 8; t++) {
                int k = kb + b_k + 2 * t;
                rB[t] = (k < NN) ? __ldg(&xcol[(size_t)k * CC]) : 0.f;
            }
        }

#pragma unroll
        for (int kk = 0; kk < BK; kk++) {
            unsigned long long a2[8];
#pragma unroll
            for (int r = 0; r < 8; r++)
                a2[r] = *(const unsigned long long*)&As2[kk * AS_LD + 16 * ty + 2 * r];
            ulonglong2 bv0 = *(const ulonglong2*)&Bs[kk * 128 + tx * 8];
            ulonglong2 bv1 = *(const ulonglong2*)&Bs[kk * 128 + tx * 8 + 4];
            unsigned long long b2[4];
            b2[0] = bv0.x;
            b2[1] = bv0.y;
            b2[2] = bv1.x;
            b2[3] = bv1.y;
#pragma unroll
            for (int r = 0; r < 8; r++)
#pragma unroll
                for (int c = 0; c < 4; c++)
                    ffma2(acc[r][c], a2[r], b2[c]);
        }
    }

    // epilogue: scale by 1/rowsum, write y1 in x layout
    const int row0 = by * 128 + ty * 8;
    const int j0   = bx * 128 + tx * 8;
    const size_t outb = (size_t)(j0 >> 6) * XSTRIDE + (j0 & 63);
#pragma unroll
    for (int r = 0; r < 8; r++) {
        int row = row0 + r;
        if (row < NN) {
            float s = g_inv[row];
#pragma unroll
            for (int c = 0; c < 4; c++) {
                float2 v = unpack2(acc[r][c]);
                float2 o = make_float2(v.x * s, v.y * s);
                *(float2*)&g_y1[outb + (size_t)row * CC + 2 * c] = o;
            }
        }
    }
}

// ============================================================================
// Kernel 4: out[b,n,o] = sum_i x[b,n,i]W0[n,i,o] + y1[b,n,i]W1[n,i,o] + bias
// 1 block per node; two 64x64x64 passes (k=0: x, k=1: y1); 4x4 microtiles.
// ============================================================================
__global__ __launch_bounds__(256) void k_out(const float* __restrict__ x,
                                             const float* __restrict__ E,
                                             const float* __restrict__ bp,
                                             float* __restrict__ out) {
    const int n = blockIdx.x;
    __shared__ __align__(16) float sIn[64 * 64];
    __shared__ __align__(16) float sW [64 * 64];
    const int tid = threadIdx.x;
    const int tx = tid & 15, ty = tid >> 4;

    float acc[4][4];
#pragma unroll
    for (int r = 0; r < 4; r++)
#pragma unroll
        for (int c = 0; c < 4; c++) acc[r][c] = 0.f;

#pragma unroll
    for (int pass = 0; pass < 2; pass++) {
        const float* src = (pass == 0) ? x : g_y1;
        __syncthreads();
#pragma unroll
        for (int t = 0; t < 16; t++) {
            int f = tid + 256 * t;          // 0..4095
            int b = f >> 6, i = f & 63;
            sIn[f] = src[(size_t)b * XSTRIDE + (size_t)n * CC + i];
            sW[f]  = g_W[(size_t)n * 8192 + pass * 4096 + f];
        }
        __syncthreads();

#pragma unroll 8
        for (int kk = 0; kk < 64; kk++) {
            float a[4];
#pragma unroll
            for (int r = 0; r < 4; r++) a[r] = sIn[(ty * 4 + r) * 64 + kk];
            float4 bv = *(const float4*)&sW[kk * 64 + tx * 4];
#pragma unroll
            for (int r = 0; r < 4; r++) {
                acc[r][0] = fmaf(a[r], bv.x, acc[r][0]);
                acc[r][1] = fmaf(a[r], bv.y, acc[r][1]);
                acc[r][2] = fmaf(a[r], bv.z, acc[r][2]);
                acc[r][3] = fmaf(a[r], bv.w, acc[r][3]);
            }
        }
    }

    // bias[o] = sum_d E[n,d]*bp[d,o]
    float bias[4];
#pragma unroll
    for (int c = 0; c < 4; c++) {
        float bsum = 0.f;
#pragma unroll
        for (int d = 0; d < DD; d++)
            bsum = fmaf(__ldg(&E[(size_t)n * DD + d]),
                        __ldg(&bp[(size_t)d * CC + tx * 4 + c]), bsum);
        bias[c] = bsum;
    }

#pragma unroll
    for (int r = 0; r < 4; r++) {
        int brow = ty * 4 + r;
        float4 o = make_float4(acc[r][0] + bias[0], acc[r][1] + bias[1],
                               acc[r][2] + bias[2], acc[r][3] + bias[3]);
        *(float4*)&out[(size_t)brow * XSTRIDE + (size_t)n * CC + tx * 4] = o;
    }
}

// ============================================================================
extern "C" void kernel_launch(void* const* d_in, const int* in_sizes, int n_in,
                              void* d_out, int out_size) {
    const float* x  = (const float*)d_in[0];   // (64,5000,64)
    const float* E  = (const float*)d_in[1];   // (5000,10)
    const float* wp = (const float*)d_in[2];   // (10,2,64,64)
    const float* bp = (const float*)d_in[3];   // (10,64)
    float* out = (float*)d_out;                // (64,5000,64)

    k_support<<<NN / 8, 256>>>(E);
    k_weights<<<dim3(32, 20), 256>>>(E, wp);
    k_gemm<<<dim3(32, 40), 256>>>(x);
    k_out<<<NN, 256>>>(x, E, bp, out);
}

// round 5
// speedup vs baseline: 2.5305x; 2.5305x over previous
#include <cuda_runtime.h>
#include <cuda_bf16.h>
#include <math.h>
#include <stdint.h>

#define NB   64
#define NN   5000
#define CC   64
#define DD   10
#define KPAD 5120
#define XSTRIDE ((size_t)NN * CC)   // 320000

// ---------------- scratch (device globals; zero-initialized at load) -------
__device__ __align__(16) __nv_bfloat16 g_Phi[(size_t)KPAD * KPAD];   // P hi (52 MB)
__device__ __align__(16) __nv_bfloat16 g_Plo[(size_t)KPAD * KPAD];   // P lo
__device__ __align__(16) __nv_bfloat16 g_Bhi[(size_t)4096 * KPAD];   // X^T hi (42 MB)
__device__ __align__(16) __nv_bfloat16 g_Blo[(size_t)4096 * KPAD];
__device__ __align__(16) float g_inv[NN];
__device__ __align__(16) float g_y1 [(size_t)NB * NN * CC];          // support @ x (82 MB)
__device__ __align__(16) float g_W  [(size_t)NN * 2 * CC * CC];      // per-node weights (164 MB)

// ---------------- helpers ----------------
__device__ __forceinline__ uint32_t smem_u32(const void* p) {
    uint32_t a;
    asm("{ .reg .u64 t; cvta.to.shared.u64 t, %1; cvt.u32.u64 %0, t; }" : "=r"(a) : "l"(p));
    return a;
}
#define CP16(so, gp)  asm volatile("cp.async.cg.shared.global [%0], [%1], 16;" :: "r"(so), "l"(gp) : "memory")
#define CP_COMMIT()   asm volatile("cp.async.commit_group;" ::: "memory")
#define CP_WAIT(n)    asm volatile("cp.async.wait_group %0;" :: "n"(n) : "memory")

#define LDMX4(r0, r1, r2, r3, addr) \
    asm volatile("ldmatrix.sync.aligned.m8n8.x4.shared.b16 {%0,%1,%2,%3}, [%4];" \
                 : "=r"(r0), "=r"(r1), "=r"(r2), "=r"(r3) : "r"(addr))

#define MMA_BF16(d, a, b0, b1) \
    asm volatile("mma.sync.aligned.m16n8k16.row.col.f32.bf16.bf16.f32 " \
                 "{%0,%1,%2,%3}, {%4,%5,%6,%7}, {%8,%9}, {%0,%1,%2,%3};" \
                 : "+f"((d)[0]), "+f"((d)[1]), "+f"((d)[2]), "+f"((d)[3]) \
                 : "r"((a)[0]), "r"((a)[1]), "r"((a)[2]), "r"((a)[3]), "r"(b0), "r"(b1))

// ============================================================================
// Kernel 1: Phi/Plo[n][m] = bf16-split of exp(relu(E[n]·E[m])); g_inv rowsum
// ============================================================================
__global__ __launch_bounds__(256) void k_support(const float* __restrict__ E) {
    const int n0 = blockIdx.x * 8;
    float e[8][DD];
#pragma unroll
    for (int r = 0; r < 8; r++)
#pragma unroll
        for (int d = 0; d < DD; d++)
            e[r][d] = __ldg(&E[(size_t)(n0 + r) * DD + d]);

    float sum[8];
#pragma unroll
    for (int r = 0; r < 8; r++) sum[r] = 0.f;

    for (int m = threadIdx.x; m < NN; m += 256) {
        float em[DD];
#pragma unroll
        for (int d = 0; d < DD; d++) em[d] = __ldg(&E[(size_t)m * DD + d]);
#pragma unroll
        for (int r = 0; r < 8; r++) {
            float dot = 0.f;
#pragma unroll
            for (int d = 0; d < DD; d++) dot = fmaf(e[r][d], em[d], dot);
            float v = expf(fmaxf(dot, 0.f));
            __nv_bfloat16 hi = __float2bfloat16(v);
            float lo = v - __bfloat162float(hi);
            g_Phi[(size_t)(n0 + r) * KPAD + m] = hi;
            g_Plo[(size_t)(n0 + r) * KPAD + m] = __float2bfloat16(lo);
            sum[r] += v;
        }
    }

    __shared__ float ss[8][256];
#pragma unroll
    for (int r = 0; r < 8; r++) ss[r][threadIdx.x] = sum[r];
    __syncthreads();
    int wid = threadIdx.x >> 5, lane = threadIdx.x & 31;
    float v = 0.f;
#pragma unroll
    for (int i = 0; i < 8; i++) v += ss[wid][lane + i * 32];
#pragma unroll
    for (int o = 16; o > 0; o >>= 1) v += __shfl_xor_sync(0xffffffffu, v, o);
    if (lane == 0) g_inv[n0 + wid] = 1.0f / v;
}

// ============================================================================
// Kernel 2: transpose+split x into Bhi/Blo[j=b*64+c][k], K-major, K padded
// ============================================================================
__global__ __launch_bounds__(256) void k_xsplit(const float* __restrict__ x) {
    const int kt = blockIdx.x;          // 0..78
    const int b  = blockIdx.y;          // 0..63
    const int k0 = kt * 64;
    const int tid = threadIdx.x;
    __shared__ float sT[64 * 65];

#pragma unroll
    for (int i = 0; i < 16; i++) {
        int idx = i * 256 + tid;
        int kk = idx >> 6, cc = idx & 63;
        float v = (k0 + kk < NN) ? x[(size_t)b * XSTRIDE + (size_t)(k0 + kk) * CC + cc] : 0.f;
        sT[cc * 65 + kk] = v;
    }
    __syncthreads();
#pragma unroll
    for (int i = 0; i < 16; i++) {
        int idx = i * 256 + tid;
        int cc = idx >> 6, kk = idx & 63;
        float v = sT[cc * 65 + kk];
        __nv_bfloat16 hi = __float2bfloat16(v);
        float lo = v - __bfloat162float(hi);
        size_t o = (size_t)(b * 64 + cc) * KPAD + k0 + kk;
        g_Bhi[o] = hi;
        g_Blo[o] = __float2bfloat16(lo);
    }
}

// ============================================================================
// Kernel 3: per-node weights g_W[n][k][i][o] = sum_d E[n][d]*wp[d][k][i][o]
// ============================================================================
__global__ __launch_bounds__(256) void k_weights(const float* __restrict__ E,
                                                 const float* __restrict__ wp) {
    const int jb = blockIdx.x;
    const int n0 = blockIdx.y * 250;
    const int tid = threadIdx.x;

    float w[DD];
#pragma unroll
    for (int d = 0; d < DD; d++)
        w[d] = __ldg(&wp[(size_t)d * 8192 + jb * 256 + tid]);

    __shared__ float sE[250 * DD];
    for (int i = tid; i < 250 * DD; i += 256)
        sE[i] = E[(size_t)n0 * DD + i];
    __syncthreads();

    for (int nl = 0; nl < 250; nl++) {
        float acc = 0.f;
#pragma unroll
        for (int d = 0; d < DD; d++)
            acc = fmaf(sE[nl * DD + d], w[d], acc);
        g_W[(size_t)(n0 + nl) * 8192 + jb * 256 + tid] = acc;
    }
}

// ============================================================================
// Kernel 4: split-bf16 GEMM on mma.sync (HMMA):
//   y1 = (1/rowsum) * P @ X;  D += Ahi*Bhi + Ahi*Blo + Alo*Bhi
//   grid (32 j-tiles of 128, 40 n-tiles of 128), 256 thr, warp tile 64x32
// ============================================================================
#define NCH        160            // 5120 / 32
#define LDROW      80             // 32 bf16 = 64B data + 16B pad (conflict-free ldmatrix)
#define TILE_B     (128 * LDROW)  // 10240 B per operand tile
#define STAGE_B    (4 * TILE_B)   // AHI, ALO, BHI, BLO
#define GEMM_SMEM  (3 * STAGE_B)  // 122880 B

__global__ __launch_bounds__(256, 1) void k_gemm_mma() {
    extern __shared__ __align__(16) char sm[];
    const uint32_t sb = smem_u32(sm);
    const int tid = threadIdx.x, lane = tid & 31, w = tid >> 5;
    const int wm = w & 1, wn = w >> 1;           // warp -> (m half, n quarter)
    const int bx = blockIdx.x, by = blockIdx.y;

    // ---- cp.async mapping: thread covers rows r0 and r0+64, 16B chunk q
    const int r0 = tid >> 2, q = tid & 3;
    const uint32_t so0 = (uint32_t)(r0 * LDROW + q * 16);
    const uint32_t so1 = so0 + 64 * LDROW;
    const size_t arow = (size_t)(by * 128 + r0) * (KPAD * 2);
    const size_t brow = (size_t)(bx * 128 + r0) * (KPAD * 2);
    const size_t rstep = (size_t)64 * (KPAD * 2);
    const char* pAh = (const char*)g_Phi + arow + q * 16;
    const char* pAl = (const char*)g_Plo + arow + q * 16;
    const char* pBh = (const char*)g_Bhi + brow + q * 16;
    const char* pBl = (const char*)g_Blo + brow + q * 16;

#define ISSUE(cc) do {                                                         \
        size_t off = (size_t)(cc) * 64;                                        \
        uint32_t st2 = sb + ((cc) % 3) * STAGE_B;                              \
        CP16(st2 + 0 * TILE_B + so0, pAh + off);                               \
        CP16(st2 + 0 * TILE_B + so1, pAh + rstep + off);                       \
        CP16(st2 + 1 * TILE_B + so0, pAl + off);                               \
        CP16(st2 + 1 * TILE_B + so1, pAl + rstep + off);                       \
        CP16(st2 + 2 * TILE_B + so0, pBh + off);                               \
        CP16(st2 + 2 * TILE_B + so1, pBh + rstep + off);                       \
        CP16(st2 + 3 * TILE_B + so0, pBl + off);                               \
        CP16(st2 + 3 * TILE_B + so1, pBl + rstep + off);                       \
        CP_COMMIT();                                                           \
    } while (0)

    // ---- ldmatrix lane offsets
    // A x4: lanes 0-15 -> rows 0-15 @k, lanes 16-31 -> rows 0-15 @k+8
    const uint32_t a_off = (uint32_t)((wm * 64 + (lane & 15)) * LDROW + (lane >> 4) * 16);
    // B x4: groups -> (j0-7,k), (j0-7,k+8), (j8-15,k), (j8-15,k+8)
    const uint32_t b_off = (uint32_t)((wn * 32 + (lane & 7) + ((lane >> 4) & 1) * 8) * LDROW
                                      + ((lane >> 3) & 1) * 16);

    float acc[4][4][4];
#pragma unroll
    for (int mt = 0; mt < 4; mt++)
#pragma unroll
        for (int nt = 0; nt < 4; nt++)
#pragma unroll
            for (int i = 0; i < 4; i++) acc[mt][nt][i] = 0.f;

    ISSUE(0);
    ISSUE(1);

    for (int c = 0; c < NCH; c++) {
        __syncthreads();                 // stage (c+2)%3 free to overwrite
        if (c + 2 < NCH)      { ISSUE(c + 2); CP_WAIT(2); }
        else if (c + 1 < NCH) { CP_WAIT(1); }
        else                  { CP_WAIT(0); }
        __syncthreads();                 // chunk c resident for all warps

        const uint32_t st = sb + (c % 3) * STAGE_B;
#pragma unroll
        for (int ks = 0; ks < 2; ks++) {
            uint32_t Ah[4][4], Al[4][4], Bh[2][4], Bl[2][4];
#pragma unroll
            for (int mt = 0; mt < 4; mt++) {
                uint32_t ad = st + a_off + mt * (16 * LDROW) + ks * 32;
                LDMX4(Ah[mt][0], Ah[mt][1], Ah[mt][2], Ah[mt][3], ad);
                LDMX4(Al[mt][0], Al[mt][1], Al[mt][2], Al[mt][3], ad + TILE_B);
            }
#pragma unroll
            for (int n2 = 0; n2 < 2; n2++) {
                uint32_t bd = st + 2 * TILE_B + b_off + n2 * (16 * LDROW) + ks * 32;
                LDMX4(Bh[n2][0], Bh[n2][1], Bh[n2][2], Bh[n2][3], bd);
                LDMX4(Bl[n2][0], Bl[n2][1], Bl[n2][2], Bl[n2][3], bd + TILE_B);
            }
#pragma unroll
            for (int mt = 0; mt < 4; mt++)
#pragma unroll
                for (int n2 = 0; n2 < 2; n2++)
#pragma unroll
                    for (int h = 0; h < 2; h++) {
                        int nt = n2 * 2 + h;
                        MMA_BF16(acc[mt][nt], Ah[mt], Bh[n2][2 * h], Bh[n2][2 * h + 1]);
                        MMA_BF16(acc[mt][nt], Ah[mt], Bl[n2][2 * h], Bl[n2][2 * h + 1]);
                        MMA_BF16(acc[mt][nt], Al[mt], Bh[n2][2 * h], Bh[n2][2 * h + 1]);
                    }
        }
    }

    // ---- epilogue: scale by 1/rowsum, write y1 in x layout (float2 stores)
#pragma unroll
    for (int mt = 0; mt < 4; mt++) {
        int rowA = by * 128 + wm * 64 + mt * 16 + (lane >> 2);
        int rowB = rowA + 8;
        float sA = (rowA < NN) ? g_inv[rowA] : 0.f;
        float sB = (rowB < NN) ? g_inv[rowB] : 0.f;
#pragma unroll
        for (int nt = 0; nt < 4; nt++) {
            int j = bx * 128 + wn * 32 + nt * 8 + 2 * (lane & 3);
            size_t cb = (size_t)(j >> 6) * XSTRIDE + (j & 63);
            if (rowA < NN) {
                float2 o = make_float2(acc[mt][nt][0] * sA, acc[mt][nt][1] * sA);
                *(float2*)&g_y1[cb + (size_t)rowA * CC] = o;
            }
            if (rowB < NN) {
                float2 o = make_float2(acc[mt][nt][2] * sB, acc[mt][nt][3] * sB);
                *(float2*)&g_y1[cb + (size_t)rowB * CC] = o;
            }
        }
    }
#undef ISSUE
}

// ============================================================================
// Kernel 5: out[b,n,o] = x[b,n,:]W0[n] + y1[b,n,:]W1[n] + bias(n)
// ============================================================================
__global__ __launch_bounds__(256) void k_out(const float* __restrict__ x,
                                             const float* __restrict__ E,
                                             const float* __restrict__ bp,
                                             float* __restrict__ out) {
    const int n = blockIdx.x;
    __shared__ __align__(16) float sIn[64 * 64];
    __shared__ __align__(16) float sW [64 * 64];
    const int tid = threadIdx.x;
    const int tx = tid & 15, ty = tid >> 4;

    float acc[4][4];
#pragma unroll
    for (int r = 0; r < 4; r++)
#pragma unroll
        for (int c = 0; c < 4; c++) acc[r][c] = 0.f;

#pragma unroll
    for (int pass = 0; pass < 2; pass++) {
        const float* src = (pass == 0) ? x : g_y1;
        __syncthreads();
#pragma unroll
        for (int t = 0; t < 16; t++) {
            int f = tid + 256 * t;
            int b = f >> 6, i = f & 63;
            sIn[f] = src[(size_t)b * XSTRIDE + (size_t)n * CC + i];
            sW[f]  = g_W[(size_t)n * 8192 + pass * 4096 + f];
        }
        __syncthreads();

#pragma unroll 8
        for (int kk = 0; kk < 64; kk++) {
            float a[4];
#pragma unroll
            for (int r = 0; r < 4; r++) a[r] = sIn[(ty * 4 + r) * 64 + kk];
            float4 bv = *(const float4*)&sW[kk * 64 + tx * 4];
#pragma unroll
            for (int r = 0; r < 4; r++) {
                acc[r][0] = fmaf(a[r], bv.x, acc[r][0]);
                acc[r][1] = fmaf(a[r], bv.y, acc[r][1]);
                acc[r][2] = fmaf(a[r], bv.z, acc[r][2]);
                acc[r][3] = fmaf(a[r], bv.w, acc[r][3]);
            }
        }
    }

    float bias[4];
#pragma unroll
    for (int c = 0; c < 4; c++) {
        float bsum = 0.f;
#pragma unroll
        for (int d = 0; d < DD; d++)
            bsum = fmaf(__ldg(&E[(size_t)n * DD + d]),
                        __ldg(&bp[(size_t)d * CC + tx * 4 + c]), bsum);
        bias[c] = bsum;
    }

#pragma unroll
    for (int r = 0; r < 4; r++) {
        int brow = ty * 4 + r;
        float4 o = make_float4(acc[r][0] + bias[0], acc[r][1] + bias[1],
                               acc[r][2] + bias[2], acc[r][3] + bias[3]);
        *(float4*)&out[(size_t)brow * XSTRIDE + (size_t)n * CC + tx * 4] = o;
    }
}

// ============================================================================
extern "C" void kernel_launch(void* const* d_in, const int* in_sizes, int n_in,
                              void* d_out, int out_size) {
    const float* x  = (const float*)d_in[0];   // (64,5000,64)
    const float* E  = (const float*)d_in[1];   // (5000,10)
    const float* wp = (const float*)d_in[2];   // (10,2,64,64)
    const float* bp = (const float*)d_in[3];   // (10,64)
    float* out = (float*)d_out;                // (64,5000,64)

    cudaFuncSetAttribute(k_gemm_mma, cudaFuncAttributeMaxDynamicSharedMemorySize, GEMM_SMEM);

    k_support<<<NN / 8, 256>>>(E);
    k_xsplit <<<dim3(79, 64), 256>>>(x);
    k_weights<<<dim3(32, 20), 256>>>(E, wp);
    k_gemm_mma<<<dim3(32, 40), 256, GEMM_SMEM>>>();
    k_out    <<<NN, 256>>>(x, E, bp, out);
}